// round 3
// baseline (speedup 1.0000x reference)
#include <cuda_runtime.h>
#include <math.h>

#define B 4
#define T 2048
#define C 1024
#define H 16
#define D 64
#define BT (B*T)
#define SCALE 0.125f

// Scratch (allocation-free rule: __device__ globals)
__device__ float g_q[(size_t)BT * C];
__device__ float g_k[(size_t)BT * C];
__device__ float g_v[(size_t)BT * C];
__device__ float g_att[(size_t)BT * C];

// ---------------------------------------------------------------------------
// GEMM: out[M,N] = (X[M,K] @ W[N,K]^T + bias[N]) * scale
// 128x128 tile, BK=8, 256 threads, 8x8 per thread, double-buffered smem.
// ---------------------------------------------------------------------------
__global__ __launch_bounds__(256, 2)
void gemm128(const float* __restrict__ X, const float* __restrict__ W,
             const float* __restrict__ bias, float* __restrict__ out,
             int M, int N, int K, float scale) {
    __shared__ __align__(16) float As[2][8][132];
    __shared__ __align__(16) float Bs[2][8][132];
    const int tid = threadIdx.x;
    const int tx = tid & 15, ty = tid >> 4;
    const int bm = blockIdx.y * 128, bn = blockIdx.x * 128;
    const int lr = tid >> 1;          // 0..127
    const int lk = (tid & 1) * 4;     // 0 or 4

    const float* Xg = X + (size_t)(bm + lr) * K + lk;
    const float* Wg = W + (size_t)(bn + lr) * K + lk;

    float acc[8][8] = {};

    float4 xa = *(const float4*)Xg;
    float4 wb = *(const float4*)Wg;
    As[0][lk+0][lr]=xa.x; As[0][lk+1][lr]=xa.y; As[0][lk+2][lr]=xa.z; As[0][lk+3][lr]=xa.w;
    Bs[0][lk+0][lr]=wb.x; Bs[0][lk+1][lr]=wb.y; Bs[0][lk+2][lr]=wb.z; Bs[0][lk+3][lr]=wb.w;
    __syncthreads();

    int buf = 0;
    for (int k0 = 8; k0 <= K; k0 += 8) {
        if (k0 < K) {
            xa = *(const float4*)(Xg + k0);
            wb = *(const float4*)(Wg + k0);
        }
#pragma unroll
        for (int kk = 0; kk < 8; kk++) {
            float4 a0 = *(const float4*)&As[buf][kk][ty*4];
            float4 a1 = *(const float4*)&As[buf][kk][ty*4+64];
            float4 b0 = *(const float4*)&Bs[buf][kk][tx*4];
            float4 b1 = *(const float4*)&Bs[buf][kk][tx*4+64];
            float ar[8] = {a0.x,a0.y,a0.z,a0.w,a1.x,a1.y,a1.z,a1.w};
            float br[8] = {b0.x,b0.y,b0.z,b0.w,b1.x,b1.y,b1.z,b1.w};
#pragma unroll
            for (int r = 0; r < 8; r++)
#pragma unroll
                for (int c = 0; c < 8; c++)
                    acc[r][c] = fmaf(ar[r], br[c], acc[r][c]);
        }
        if (k0 < K) {
            int nb = buf ^ 1;
            As[nb][lk+0][lr]=xa.x; As[nb][lk+1][lr]=xa.y; As[nb][lk+2][lr]=xa.z; As[nb][lk+3][lr]=xa.w;
            Bs[nb][lk+0][lr]=wb.x; Bs[nb][lk+1][lr]=wb.y; Bs[nb][lk+2][lr]=wb.z; Bs[nb][lk+3][lr]=wb.w;
        }
        __syncthreads();
        buf ^= 1;
    }

    float4 bb0 = *(const float4*)(bias + bn + tx*4);
    float4 bb1 = *(const float4*)(bias + bn + 64 + tx*4);
    float bl[8] = {bb0.x,bb0.y,bb0.z,bb0.w,bb1.x,bb1.y,bb1.z,bb1.w};
#pragma unroll
    for (int r = 0; r < 8; r++) {
        int row = bm + ((r < 4) ? (ty*4 + r) : (64 + ty*4 + r - 4));
        float4 o0, o1;
        o0.x=(acc[r][0]+bl[0])*scale; o0.y=(acc[r][1]+bl[1])*scale;
        o0.z=(acc[r][2]+bl[2])*scale; o0.w=(acc[r][3]+bl[3])*scale;
        o1.x=(acc[r][4]+bl[4])*scale; o1.y=(acc[r][5]+bl[5])*scale;
        o1.z=(acc[r][6]+bl[6])*scale; o1.w=(acc[r][7]+bl[7])*scale;
        *(float4*)(out + (size_t)row * N + bn + tx*4)      = o0;
        *(float4*)(out + (size_t)row * N + bn + 64 + tx*4) = o1;
    }
}

// ---------------------------------------------------------------------------
// Scores: S[bh,i,j] = Q[b,i,h,:] . K[b,j,h,:]  (lower-triangle 128x128 tiles)
// ---------------------------------------------------------------------------
__global__ __launch_bounds__(256, 2)
void scores128(const float* __restrict__ q, const float* __restrict__ k,
               float* __restrict__ attn) {
    const int kt = blockIdx.x, qt = blockIdx.y, bh = blockIdx.z;
    if (kt > qt) return;
    const int b = bh >> 4, h = bh & 15;

    __shared__ __align__(16) float Qs[2][8][132];
    __shared__ __align__(16) float Ks[2][8][132];
    const int tid = threadIdx.x;
    const int tx = tid & 15, ty = tid >> 4;
    const int lr = tid >> 1;
    const int lk = (tid & 1) * 4;

    const float* Xg = q + (size_t)(b*T + qt*128 + lr) * C + h*64 + lk;
    const float* Wg = k + (size_t)(b*T + kt*128 + lr) * C + h*64 + lk;

    float acc[8][8] = {};

    float4 xa = *(const float4*)Xg;
    float4 wb = *(const float4*)Wg;
    Qs[0][lk+0][lr]=xa.x; Qs[0][lk+1][lr]=xa.y; Qs[0][lk+2][lr]=xa.z; Qs[0][lk+3][lr]=xa.w;
    Ks[0][lk+0][lr]=wb.x; Ks[0][lk+1][lr]=wb.y; Ks[0][lk+2][lr]=wb.z; Ks[0][lk+3][lr]=wb.w;
    __syncthreads();

    int buf = 0;
    for (int k0 = 8; k0 <= 64; k0 += 8) {
        if (k0 < 64) {
            xa = *(const float4*)(Xg + k0);
            wb = *(const float4*)(Wg + k0);
        }
#pragma unroll
        for (int kk = 0; kk < 8; kk++) {
            float4 a0 = *(const float4*)&Qs[buf][kk][ty*4];
            float4 a1 = *(const float4*)&Qs[buf][kk][ty*4+64];
            float4 b0 = *(const float4*)&Ks[buf][kk][tx*4];
            float4 b1 = *(const float4*)&Ks[buf][kk][tx*4+64];
            float ar[8] = {a0.x,a0.y,a0.z,a0.w,a1.x,a1.y,a1.z,a1.w};
            float br[8] = {b0.x,b0.y,b0.z,b0.w,b1.x,b1.y,b1.z,b1.w};
#pragma unroll
            for (int r = 0; r < 8; r++)
#pragma unroll
                for (int c = 0; c < 8; c++)
                    acc[r][c] = fmaf(ar[r], br[c], acc[r][c]);
        }
        if (k0 < 64) {
            int nb = buf ^ 1;
            Qs[nb][lk+0][lr]=xa.x; Qs[nb][lk+1][lr]=xa.y; Qs[nb][lk+2][lr]=xa.z; Qs[nb][lk+3][lr]=xa.w;
            Ks[nb][lk+0][lr]=wb.x; Ks[nb][lk+1][lr]=wb.y; Ks[nb][lk+2][lr]=wb.z; Ks[nb][lk+3][lr]=wb.w;
        }
        __syncthreads();
        buf ^= 1;
    }

    float* og = attn + (size_t)bh * T * T + (size_t)(qt*128) * T + kt*128;
#pragma unroll
    for (int r = 0; r < 8; r++) {
        int row = (r < 4) ? (ty*4 + r) : (64 + ty*4 + r - 4);
        float4 o0 = {acc[r][0], acc[r][1], acc[r][2], acc[r][3]};
        float4 o1 = {acc[r][4], acc[r][5], acc[r][6], acc[r][7]};
        *(float4*)(og + (size_t)row * T + tx*4)      = o0;
        *(float4*)(og + (size_t)row * T + 64 + tx*4) = o1;
    }
}

// ---------------------------------------------------------------------------
// Softmax per row; causal, honors key_padding_mask, zero-fills j>i.
// ---------------------------------------------------------------------------
__global__ void softmax_kernel(float* __restrict__ attn, const unsigned char* __restrict__ kp) {
    const int i = blockIdx.x;
    const int bh = blockIdx.y;
    const int b = bh >> 4;
    float* row = attn + (size_t)bh * T * T + (size_t)i * T;
    const int tid = threadIdx.x;
    const int len = i + 1;

    float vals[8];
    unsigned char msk[8];
    int nk = 0;
    float m = -INFINITY;
    for (int j = tid; j < len; j += 256) {
        float s = row[j];
        unsigned char pm = kp[b * T + j];
        vals[nk] = s; msk[nk] = pm; nk++;
        if (!pm) m = fmaxf(m, s);
    }

    __shared__ float red[256];
    red[tid] = m; __syncthreads();
    for (int off = 128; off > 0; off >>= 1) {
        if (tid < off) red[tid] = fmaxf(red[tid], red[tid + off]);
        __syncthreads();
    }
    m = red[0];
    __syncthreads();

    float sum = 0.f;
    for (int t = 0; t < nk; t++) {
        float e = msk[t] ? 0.f : __expf(vals[t] - m);
        vals[t] = e;
        sum += e;
    }
    red[tid] = sum; __syncthreads();
    for (int off = 128; off > 0; off >>= 1) {
        if (tid < off) red[tid] += red[tid + off];
        __syncthreads();
    }
    float inv = 1.0f / red[0];

    int t2 = 0;
    for (int j = tid; j < len; j += 256) row[j] = vals[t2++] * inv;
    for (int j = len + tid; j < T; j += 256) row[j] = 0.f;
}

// ---------------------------------------------------------------------------
// O = P @ V per (b,h,q128tile). 128x64 out tile, 8x4 per thread, k-slabs of 64.
// ---------------------------------------------------------------------------
__global__ __launch_bounds__(256)
void av128(const float* __restrict__ attn, const float* __restrict__ v,
           float* __restrict__ out) {
    const int qt = blockIdx.x, bh = blockIdx.y;
    const int b = bh >> 4, h = bh & 15;

    __shared__ __align__(16) float Ps[64][132];   // [k][m]
    __shared__ __align__(16) float Vs[64][68];    // [k][n]
    const int tid = threadIdx.x;
    const int tx = tid & 15, ty = tid >> 4;
    const int pr = tid >> 1;            // 0..127 (P row)
    const int pc0 = (tid & 1) * 4;      // 0 or 4

    float acc[8][4] = {};
    const int nkt = 2 * qt + 2;         // 64-wide key tiles covering causal span

    for (int kt = 0; kt < nkt; kt++) {
        const float* pg = attn + (size_t)bh * T * T + (size_t)(qt*128 + pr) * T + kt*64;
#pragma unroll
        for (int i = 0; i < 8; i++) {
            int col = pc0 + i * 8;
            float4 p = *(const float4*)(pg + col);
            Ps[col+0][pr] = p.x; Ps[col+1][pr] = p.y;
            Ps[col+2][pr] = p.z; Ps[col+3][pr] = p.w;
        }
#pragma unroll
        for (int i = 0; i < 4; i++) {
            int idx = tid + i * 256;
            int vr = idx >> 4;
            int vc = (idx & 15) * 4;
            *(float4*)&Vs[vr][vc] =
                *(const float4*)(v + (size_t)(b*T + kt*64 + vr) * C + h*64 + vc);
        }
        __syncthreads();

#pragma unroll 8
        for (int kk = 0; kk < 64; kk++) {
            float4 p0 = *(const float4*)&Ps[kk][ty*4];
            float4 p1 = *(const float4*)&Ps[kk][ty*4+64];
            float4 vv = *(const float4*)&Vs[kk][tx*4];
            float pr8[8] = {p0.x,p0.y,p0.z,p0.w,p1.x,p1.y,p1.z,p1.w};
            float vr4[4] = {vv.x,vv.y,vv.z,vv.w};
#pragma unroll
            for (int r = 0; r < 8; r++)
#pragma unroll
                for (int c = 0; c < 4; c++)
                    acc[r][c] = fmaf(pr8[r], vr4[c], acc[r][c]);
        }
        __syncthreads();
    }

#pragma unroll
    for (int r = 0; r < 8; r++) {
        int row = (r < 4) ? (ty*4 + r) : (64 + ty*4 + r - 4);
        float4 o = {acc[r][0], acc[r][1], acc[r][2], acc[r][3]};
        *(float4*)(out + (size_t)(b*T + qt*128 + row) * C + h*64 + tx*4) = o;
    }
}

// ---------------------------------------------------------------------------
extern "C" void kernel_launch(void* const* d_in, const int* in_sizes, int n_in,
                              void* d_out, int out_size) {
    const float* query = (const float*)d_in[0];
    const float* key   = (const float*)d_in[1];
    const float* value = (const float*)d_in[2];
    // d_in[3] = attn_mask (causal triu, hardcoded)
    const unsigned char* kp = (const unsigned char*)d_in[4];
    const float* Wq = (const float*)d_in[5];  const float* bq = (const float*)d_in[6];
    const float* Wk = (const float*)d_in[7];  const float* bk = (const float*)d_in[8];
    const float* Wv = (const float*)d_in[9];  const float* bv = (const float*)d_in[10];
    const float* Wo = (const float*)d_in[11]; const float* bo = (const float*)d_in[12];

    float* y    = (float*)d_out;
    float* attn = y + (size_t)BT * C;  // tuple order: (y, attn_weights)

    float *gq, *gk, *gv, *gatt;
    cudaGetSymbolAddress((void**)&gq, g_q);
    cudaGetSymbolAddress((void**)&gk, g_k);
    cudaGetSymbolAddress((void**)&gv, g_v);
    cudaGetSymbolAddress((void**)&gatt, g_att);

    dim3 ggrid(C / 128, BT / 128);  // (8, 64)

    // Q/K/V projections (SCALE folded into Q)
    gemm128<<<ggrid, 256>>>(query, Wq, bq, gq, BT, C, C, SCALE);
    gemm128<<<ggrid, 256>>>(key,   Wk, bk, gk, BT, C, C, 1.0f);
    gemm128<<<ggrid, 256>>>(value, Wv, bv, gv, BT, C, C, 1.0f);

    // Scores (lower-triangle 128x128 tiles)
    dim3 sgrid(T / 128, T / 128, B * H);  // (16, 16, 64)
    scores128<<<sgrid, 256>>>(gq, gk, attn);

    // Row softmax + zero-fill masked region
    dim3 smgrid(T, B * H);
    softmax_kernel<<<smgrid, 256>>>(attn, kp);

    // P @ V
    dim3 avgrid(T / 128, B * H);  // (16, 64)
    av128<<<avgrid, 256>>>(attn, gv, gatt);

    // Output projection
    gemm128<<<ggrid, 256>>>(gatt, Wo, bo, y, BT, C, C, 1.0f);
}

// round 5
// speedup vs baseline: 1.2830x; 1.2830x over previous
#include <cuda_runtime.h>
#include <cuda_bf16.h>
#include <math.h>
#include <stdint.h>

#define B 4
#define T 2048
#define C 1024
#define H 16
#define D 64
#define BT (B*T)
#define SCALE 0.125f

typedef __nv_bfloat16 bf16;

// ---------------- scratch (__device__ globals; no allocs allowed) ----------
__device__ bf16 g_qh[(size_t)BT*C], g_ql[(size_t)BT*C];
__device__ bf16 g_kh[(size_t)BT*C], g_kl[(size_t)BT*C];
__device__ bf16 g_vh[(size_t)BT*C], g_vl[(size_t)BT*C];
__device__ bf16 g_ah[(size_t)BT*C], g_al[(size_t)BT*C];

// ---------------- helpers ---------------------------------------------------
__device__ __forceinline__ uint32_t smem_u32(const void* p) {
    uint32_t a;
    asm("{ .reg .u64 t; cvta.to.shared.u64 t, %1; cvt.u32.u64 %0, t; }" : "=r"(a) : "l"(p));
    return a;
}
__device__ __forceinline__ void ldsm4(uint32_t a, uint32_t r[4]) {
    asm volatile("ldmatrix.sync.aligned.m8n8.x4.shared.b16 {%0,%1,%2,%3}, [%4];"
                 : "=r"(r[0]), "=r"(r[1]), "=r"(r[2]), "=r"(r[3]) : "r"(a));
}
__device__ __forceinline__ void ldsm2(uint32_t a, uint32_t r[2]) {
    asm volatile("ldmatrix.sync.aligned.m8n8.x2.shared.b16 {%0,%1}, [%2];"
                 : "=r"(r[0]), "=r"(r[1]) : "r"(a));
}
__device__ __forceinline__ void ldsm2t(uint32_t a, uint32_t r[2]) {
    asm volatile("ldmatrix.sync.aligned.m8n8.x2.trans.shared.b16 {%0,%1}, [%2];"
                 : "=r"(r[0]), "=r"(r[1]) : "r"(a));
}
__device__ __forceinline__ void mma_bf16(float c[4], const uint32_t a[4], const uint32_t b2[2]) {
    asm volatile("mma.sync.aligned.m16n8k16.row.col.f32.bf16.bf16.f32 "
                 "{%0,%1,%2,%3}, {%4,%5,%6,%7}, {%8,%9}, {%0,%1,%2,%3};"
                 : "+f"(c[0]), "+f"(c[1]), "+f"(c[2]), "+f"(c[3])
                 : "r"(a[0]), "r"(a[1]), "r"(a[2]), "r"(a[3]), "r"(b2[0]), "r"(b2[1]));
}
__device__ __forceinline__ uint32_t pack2(bf16 a, bf16 b) {
    __nv_bfloat162 t = __halves2bfloat162(a, b);
    return *(uint32_t*)&t;
}
__device__ __forceinline__ void fsplit(float v, bf16& h, bf16& l) {
    h = __float2bfloat16(v);
    l = __float2bfloat16(v - __bfloat162float(h));
}
// convert 16 contiguous fp32 -> 16 bf16 hi + 16 bf16 lo
__device__ __forceinline__ void stage16_f32(const float* src, bf16* dh, bf16* dl) {
#pragma unroll
    for (int j = 0; j < 16; j += 4) {
        float4 v = *(const float4*)(src + j);
        bf16 h0,h1,h2,h3,l0,l1,l2,l3;
        fsplit(v.x,h0,l0); fsplit(v.y,h1,l1); fsplit(v.z,h2,l2); fsplit(v.w,h3,l3);
        *(uint2*)(dh + j) = make_uint2(pack2(h0,h1), pack2(h2,h3));
        *(uint2*)(dl + j) = make_uint2(pack2(l0,l1), pack2(l2,l3));
    }
}

// ---------------------------------------------------------------------------
// Projection GEMM on tensor cores: out[M=BT,N=C] = (X @ W^T + bias) * scale
// MODE 0: X fp32 -> write split bf16 (outh/outl).  MODE 1: X split -> fp32 out.
// 128x128 tile, BK=32, 256 thr (8 warps, 2x4, warp tile 64x32), dbl-buffered.
// ---------------------------------------------------------------------------
#define PROJ_SMEM (8 * 5120 * 2)

template<int MODE>
__global__ __launch_bounds__(256, 1)
void proj_tc(const float* __restrict__ Xf,
             const bf16* __restrict__ Xh, const bf16* __restrict__ Xl,
             const float* __restrict__ W, const float* __restrict__ bias,
             float scale,
             float* __restrict__ outf, bf16* __restrict__ outh, bf16* __restrict__ outl) {
    extern __shared__ char smc[];
    bf16* sAh = (bf16*)smc;          // [2][128*40]
    bf16* sAl = sAh + 2 * 5120;
    bf16* sBh = sAl + 2 * 5120;
    bf16* sBl = sBh + 2 * 5120;

    const int tid = threadIdx.x;
    const int wid = tid >> 5, lane = tid & 31;
    const int bm = blockIdx.y * 128, bn = blockIdx.x * 128;
    const int wm = (wid >> 2) * 64, wn = (wid & 3) * 32;
    const int srow = tid >> 1, scb = (tid & 1) * 16;   // staging: 16 cols of one row

    float acc[4][4][4] = {};

    // ---- prologue: stage chunk 0 ----
    {
        bf16* dh = sAh + srow * 40 + scb;
        bf16* dl = sAl + srow * 40 + scb;
        if (MODE == 0) {
            stage16_f32(Xf + (size_t)(bm + srow) * C + scb, dh, dl);
        } else {
            const bf16* xh = Xh + (size_t)(bm + srow) * C + scb;
            const bf16* xl = Xl + (size_t)(bm + srow) * C + scb;
            *(uint4*)dh = *(const uint4*)xh; *(uint4*)(dh + 8) = *(const uint4*)(xh + 8);
            *(uint4*)dl = *(const uint4*)xl; *(uint4*)(dl + 8) = *(const uint4*)(xl + 8);
        }
        stage16_f32(W + (size_t)(bn + srow) * C + scb, sBh + srow * 40 + scb, sBl + srow * 40 + scb);
    }
    __syncthreads();

    for (int c = 0; c < 32; c++) {
        const int buf = c & 1;
        if (c + 1 < 32) {
            const int k0 = (c + 1) * 32;
            const int nb = buf ^ 1;
            bf16* dh = sAh + nb * 5120 + srow * 40 + scb;
            bf16* dl = sAl + nb * 5120 + srow * 40 + scb;
            if (MODE == 0) {
                stage16_f32(Xf + (size_t)(bm + srow) * C + k0 + scb, dh, dl);
            } else {
                const bf16* xh = Xh + (size_t)(bm + srow) * C + k0 + scb;
                const bf16* xl = Xl + (size_t)(bm + srow) * C + k0 + scb;
                *(uint4*)dh = *(const uint4*)xh; *(uint4*)(dh + 8) = *(const uint4*)(xh + 8);
                *(uint4*)dl = *(const uint4*)xl; *(uint4*)(dl + 8) = *(const uint4*)(xl + 8);
            }
            stage16_f32(W + (size_t)(bn + srow) * C + k0 + scb,
                        sBh + nb * 5120 + srow * 40 + scb, sBl + nb * 5120 + srow * 40 + scb);
        }
        // ---- compute on buf ----
        const uint32_t bAh = smem_u32(sAh + buf * 5120);
        const uint32_t bAl = smem_u32(sAl + buf * 5120);
        const uint32_t bBh = smem_u32(sBh + buf * 5120);
        const uint32_t bBl = smem_u32(sBl + buf * 5120);
#pragma unroll
        for (int s = 0; s < 2; s++) {
            uint32_t afh[4][4], afl[4][4], fbh[4][2], fbl[4][2];
#pragma unroll
            for (int mf = 0; mf < 4; mf++) {
                uint32_t off = (uint32_t)(wm + mf * 16 + (lane & 15)) * 80 + s * 32 + ((lane >> 4) * 16);
                ldsm4(bAh + off, afh[mf]);
                ldsm4(bAl + off, afl[mf]);
            }
#pragma unroll
            for (int nf = 0; nf < 4; nf++) {
                uint32_t off = (uint32_t)(wn + nf * 8 + (lane & 7)) * 80 + s * 32 + (((lane >> 3) & 1) * 16);
                ldsm2(bBh + off, fbh[nf]);
                ldsm2(bBl + off, fbl[nf]);
            }
#pragma unroll
            for (int mf = 0; mf < 4; mf++)
#pragma unroll
                for (int nf = 0; nf < 4; nf++) {
                    mma_bf16(acc[mf][nf], afh[mf], fbh[nf]);
                    mma_bf16(acc[mf][nf], afh[mf], fbl[nf]);
                    mma_bf16(acc[mf][nf], afl[mf], fbh[nf]);
                }
        }
        __syncthreads();
    }

    // ---- epilogue ----
#pragma unroll
    for (int mf = 0; mf < 4; mf++) {
        const int gr = bm + wm + mf * 16 + (lane >> 2);
#pragma unroll
        for (int nf = 0; nf < 4; nf++) {
            const int gc = bn + wn + nf * 8 + (lane & 3) * 2;
            float b0 = bias[gc], b1 = bias[gc + 1];
            float v0 = (acc[mf][nf][0] + b0) * scale;
            float v1 = (acc[mf][nf][1] + b1) * scale;
            float v2 = (acc[mf][nf][2] + b0) * scale;
            float v3 = (acc[mf][nf][3] + b1) * scale;
            if (MODE == 0) {
                bf16 h0,h1,l0,l1; fsplit(v0,h0,l0); fsplit(v1,h1,l1);
                *(uint32_t*)(outh + (size_t)gr * C + gc) = pack2(h0, h1);
                *(uint32_t*)(outl + (size_t)gr * C + gc) = pack2(l0, l1);
                fsplit(v2,h0,l0); fsplit(v3,h1,l1);
                *(uint32_t*)(outh + (size_t)(gr + 8) * C + gc) = pack2(h0, h1);
                *(uint32_t*)(outl + (size_t)(gr + 8) * C + gc) = pack2(l0, l1);
            } else {
                *(float2*)(outf + (size_t)gr * C + gc)       = make_float2(v0, v1);
                *(float2*)(outf + (size_t)(gr + 8) * C + gc) = make_float2(v2, v3);
            }
        }
    }
}

// ---------------------------------------------------------------------------
// Scores: S = Q . K^T per (b,h), lower-triangle 128x128 tiles, K=64 single-shot
// ---------------------------------------------------------------------------
#define SCORES_SMEM (4 * 9216 * 2)

__global__ __launch_bounds__(256, 1)
void scores_tc(const bf16* __restrict__ qh, const bf16* __restrict__ ql,
               const bf16* __restrict__ kh, const bf16* __restrict__ kl,
               float* __restrict__ attn) {
    const int kt = blockIdx.x, qt = blockIdx.y, bh = blockIdx.z;
    if (kt > qt) return;
    const int b = bh >> 4, h = bh & 15;

    extern __shared__ char smc[];
    bf16* sQh = (bf16*)smc;          // [128*72]
    bf16* sQl = sQh + 9216;
    bf16* sKh = sQl + 9216;
    bf16* sKl = sKh + 9216;

    const int tid = threadIdx.x;
    const int wid = tid >> 5, lane = tid & 31;
    const int wm = (wid >> 2) * 64, wn = (wid & 3) * 32;
    const int srow = tid >> 1, scb = (tid & 1) * 32;   // 32 cols of one row

    {
        const size_t qoff = (size_t)(b * T + qt * 128 + srow) * C + h * 64 + scb;
        const size_t koff = (size_t)(b * T + kt * 128 + srow) * C + h * 64 + scb;
        bf16* d;
        d = sQh + srow * 72 + scb;
#pragma unroll
        for (int j = 0; j < 32; j += 8) *(uint4*)(d + j) = *(const uint4*)(qh + qoff + j);
        d = sQl + srow * 72 + scb;
#pragma unroll
        for (int j = 0; j < 32; j += 8) *(uint4*)(d + j) = *(const uint4*)(ql + qoff + j);
        d = sKh + srow * 72 + scb;
#pragma unroll
        for (int j = 0; j < 32; j += 8) *(uint4*)(d + j) = *(const uint4*)(kh + koff + j);
        d = sKl + srow * 72 + scb;
#pragma unroll
        for (int j = 0; j < 32; j += 8) *(uint4*)(d + j) = *(const uint4*)(kl + koff + j);
    }
    __syncthreads();

    float acc[4][4][4] = {};
    const uint32_t bQh = smem_u32(sQh), bQl = smem_u32(sQl);
    const uint32_t bKh = smem_u32(sKh), bKl = smem_u32(sKl);

#pragma unroll
    for (int s = 0; s < 4; s++) {
        uint32_t afh[4][4], afl[4][4], fbh[4][2], fbl[4][2];
#pragma unroll
        for (int mf = 0; mf < 4; mf++) {
            uint32_t off = (uint32_t)(wm + mf * 16 + (lane & 15)) * 144 + s * 32 + ((lane >> 4) * 16);
            ldsm4(bQh + off, afh[mf]);
            ldsm4(bQl + off, afl[mf]);
        }
#pragma unroll
        for (int nf = 0; nf < 4; nf++) {
            uint32_t off = (uint32_t)(wn + nf * 8 + (lane & 7)) * 144 + s * 32 + (((lane >> 3) & 1) * 16);
            ldsm2(bKh + off, fbh[nf]);
            ldsm2(bKl + off, fbl[nf]);
        }
#pragma unroll
        for (int mf = 0; mf < 4; mf++)
#pragma unroll
            for (int nf = 0; nf < 4; nf++) {
                mma_bf16(acc[mf][nf], afh[mf], fbh[nf]);
                mma_bf16(acc[mf][nf], afh[mf], fbl[nf]);
                mma_bf16(acc[mf][nf], afl[mf], fbh[nf]);
            }
    }

    float* ab = attn + (size_t)bh * T * T;
#pragma unroll
    for (int mf = 0; mf < 4; mf++) {
        const int gr = qt * 128 + wm + mf * 16 + (lane >> 2);
#pragma unroll
        for (int nf = 0; nf < 4; nf++) {
            const int gc = kt * 128 + wn + nf * 8 + (lane & 3) * 2;
            *(float2*)(ab + (size_t)gr * T + gc)       = make_float2(acc[mf][nf][0], acc[mf][nf][1]);
            *(float2*)(ab + (size_t)(gr + 8) * T + gc) = make_float2(acc[mf][nf][2], acc[mf][nf][3]);
        }
    }
}

// ---------------------------------------------------------------------------
// Softmax per row; causal, honors key_padding_mask, zero-fills j>i.
// ---------------------------------------------------------------------------
__global__ void softmax_kernel(float* __restrict__ attn, const unsigned char* __restrict__ kp) {
    const int i = blockIdx.x;
    const int bh = blockIdx.y;
    const int b = bh >> 4;
    float* row = attn + (size_t)bh * T * T + (size_t)i * T;
    const int tid = threadIdx.x;
    const int len = i + 1;

    float vals[8];
    unsigned char msk[8];
    int nk = 0;
    float m = -INFINITY;
    for (int j = tid; j < len; j += 256) {
        float s = row[j];
        unsigned char pm = kp[b * T + j];
        vals[nk] = s; msk[nk] = pm; nk++;
        if (!pm) m = fmaxf(m, s);
    }

    __shared__ float red[256];
    red[tid] = m; __syncthreads();
    for (int off = 128; off > 0; off >>= 1) {
        if (tid < off) red[tid] = fmaxf(red[tid], red[tid + off]);
        __syncthreads();
    }
    m = red[0];
    __syncthreads();

    float sum = 0.f;
    for (int t = 0; t < nk; t++) {
        float e = msk[t] ? 0.f : __expf(vals[t] - m);
        vals[t] = e;
        sum += e;
    }
    red[tid] = sum; __syncthreads();
    for (int off = 128; off > 0; off >>= 1) {
        if (tid < off) red[tid] += red[tid + off];
        __syncthreads();
    }
    float inv = 1.0f / red[0];

    int t2 = 0;
    for (int j = tid; j < len; j += 256) row[j] = vals[t2++] * inv;
    for (int j = len + tid; j < T; j += 256) row[j] = 0.f;
}

// ---------------------------------------------------------------------------
// AV: O = P @ V per (qt, bh); 128x64 tile, warp tile 64x16, BK=32 slabs.
// P converted fp32->bf16 hi/lo in-kernel; output written as split bf16.
// ---------------------------------------------------------------------------
#define AV_SMEM ((2 * 5120 + 2 * 2304) * 2)

__global__ __launch_bounds__(256, 1)
void av_tc(const float* __restrict__ attn, const bf16* __restrict__ vh,
           const bf16* __restrict__ vl, bf16* __restrict__ outh, bf16* __restrict__ outl) {
    const int qt = blockIdx.x, bh = blockIdx.y;
    const int b = bh >> 4, h = bh & 15;

    extern __shared__ char smc[];
    bf16* sPh = (bf16*)smc;          // [128*40]
    bf16* sPl = sPh + 5120;
    bf16* sVh = sPl + 5120;          // [32*72]
    bf16* sVl = sVh + 2304;

    const int tid = threadIdx.x;
    const int wid = tid >> 5, lane = tid & 31;
    const int wm = (wid >> 2) * 64, wn = (wid & 3) * 16;
    const int prow = tid >> 1, pcb = (tid & 1) * 16;   // P staging: 16 cols of a row
    const int vrow = tid >> 3, vcb = (tid & 7) * 8;    // V staging: 8 cols of a row

    float acc[4][2][4] = {};
    const int nkt = 4 * qt + 4;

    const uint32_t bPh = smem_u32(sPh), bPl = smem_u32(sPl);
    const uint32_t bVh = smem_u32(sVh), bVl = smem_u32(sVl);

    for (int kt = 0; kt < nkt; kt++) {
        const int t0 = kt * 32;
        stage16_f32(attn + (size_t)bh * T * T + (size_t)(qt * 128 + prow) * T + t0 + pcb,
                    sPh + prow * 40 + pcb, sPl + prow * 40 + pcb);
        {
            const size_t voff = (size_t)(b * T + t0 + vrow) * C + h * 64 + vcb;
            *(uint4*)(sVh + vrow * 72 + vcb) = *(const uint4*)(vh + voff);
            *(uint4*)(sVl + vrow * 72 + vcb) = *(const uint4*)(vl + voff);
        }
        __syncthreads();

#pragma unroll
        for (int s = 0; s < 2; s++) {
            uint32_t afh[4][4], afl[4][4], fbh[2][2], fbl[2][2];
#pragma unroll
            for (int mf = 0; mf < 4; mf++) {
                uint32_t off = (uint32_t)(wm + mf * 16 + (lane & 15)) * 80 + s * 32 + ((lane >> 4) * 16);
                ldsm4(bPh + off, afh[mf]);
                ldsm4(bPl + off, afl[mf]);
            }
#pragma unroll
            for (int nf = 0; nf < 2; nf++) {
                uint32_t off = (uint32_t)(s * 16 + (lane & 15)) * 144 + (wn + nf * 8) * 2;
                ldsm2t(bVh + off, fbh[nf]);
                ldsm2t(bVl + off, fbl[nf]);
            }
#pragma unroll
            for (int mf = 0; mf < 4; mf++)
#pragma unroll
                for (int nf = 0; nf < 2; nf++) {
                    mma_bf16(acc[mf][nf], afh[mf], fbh[nf]);
                    mma_bf16(acc[mf][nf], afh[mf], fbl[nf]);
                    mma_bf16(acc[mf][nf], afl[mf], fbh[nf]);
                }
        }
        __syncthreads();
    }

#pragma unroll
    for (int mf = 0; mf < 4; mf++) {
        const int gr = b * T + qt * 128 + wm + mf * 16 + (lane >> 2);
#pragma unroll
        for (int nf = 0; nf < 2; nf++) {
            const int gc = h * 64 + wn + nf * 8 + (lane & 3) * 2;
            bf16 h0,h1,l0,l1;
            fsplit(acc[mf][nf][0], h0, l0); fsplit(acc[mf][nf][1], h1, l1);
            *(uint32_t*)(outh + (size_t)gr * C + gc) = pack2(h0, h1);
            *(uint32_t*)(outl + (size_t)gr * C + gc) = pack2(l0, l1);
            fsplit(acc[mf][nf][2], h0, l0); fsplit(acc[mf][nf][3], h1, l1);
            *(uint32_t*)(outh + (size_t)(gr + 8) * C + gc) = pack2(h0, h1);
            *(uint32_t*)(outl + (size_t)(gr + 8) * C + gc) = pack2(l0, l1);
        }
    }
}

// ---------------------------------------------------------------------------
extern "C" void kernel_launch(void* const* d_in, const int* in_sizes, int n_in,
                              void* d_out, int out_size) {
    const float* query = (const float*)d_in[0];
    const float* key   = (const float*)d_in[1];
    const float* value = (const float*)d_in[2];
    const unsigned char* kp = (const unsigned char*)d_in[4];
    const float* Wq = (const float*)d_in[5];  const float* bq = (const float*)d_in[6];
    const float* Wk = (const float*)d_in[7];  const float* bk = (const float*)d_in[8];
    const float* Wv = (const float*)d_in[9];  const float* bv = (const float*)d_in[10];
    const float* Wo = (const float*)d_in[11]; const float* bo = (const float*)d_in[12];

    float* y    = (float*)d_out;
    float* attn = y + (size_t)BT * C;   // tuple order: (y, attn_weights)

    bf16 *qh,*ql,*kh,*kl,*vh,*vl,*ah,*al;
    cudaGetSymbolAddress((void**)&qh, g_qh); cudaGetSymbolAddress((void**)&ql, g_ql);
    cudaGetSymbolAddress((void**)&kh, g_kh); cudaGetSymbolAddress((void**)&kl, g_kl);
    cudaGetSymbolAddress((void**)&vh, g_vh); cudaGetSymbolAddress((void**)&vl, g_vl);
    cudaGetSymbolAddress((void**)&ah, g_ah); cudaGetSymbolAddress((void**)&al, g_al);

    cudaFuncSetAttribute(proj_tc<0>, cudaFuncAttributeMaxDynamicSharedMemorySize, PROJ_SMEM);
    cudaFuncSetAttribute(proj_tc<1>, cudaFuncAttributeMaxDynamicSharedMemorySize, PROJ_SMEM);
    cudaFuncSetAttribute(scores_tc,  cudaFuncAttributeMaxDynamicSharedMemorySize, SCORES_SMEM);

    dim3 pg(C / 128, BT / 128);   // (8, 64)

    // projections (SCALE folded into Q); write split bf16 Q/K/V directly
    proj_tc<0><<<pg, 256, PROJ_SMEM>>>(query, nullptr, nullptr, Wq, bq, SCALE, nullptr, qh, ql);
    proj_tc<0><<<pg, 256, PROJ_SMEM>>>(key,   nullptr, nullptr, Wk, bk, 1.0f,  nullptr, kh, kl);
    proj_tc<0><<<pg, 256, PROJ_SMEM>>>(value, nullptr, nullptr, Wv, bv, 1.0f,  nullptr, vh, vl);

    // scores (lower-triangle 128x128 tiles)
    dim3 sg(T / 128, T / 128, B * H);  // (16, 16, 64)
    scores_tc<<<sg, 256, SCORES_SMEM>>>(qh, ql, kh, kl, attn);

    // row softmax + zero-fill masked region
    dim3 smg(T, B * H);
    softmax_kernel<<<smg, 256>>>(attn, kp);

    // P @ V -> split bf16 attention output
    dim3 ag(T / 128, B * H);           // (16, 64)
    av_tc<<<ag, 256, AV_SMEM>>>(attn, vh, vl, ah, al);

    // output projection (split X -> fp32 y)
    proj_tc<1><<<pg, 256, PROJ_SMEM>>>(nullptr, ah, al, Wo, bo, 1.0f, y, nullptr, nullptr);
}

// round 6
// speedup vs baseline: 1.4664x; 1.1429x over previous
#include <cuda_runtime.h>
#include <cuda_bf16.h>
#include <math.h>
#include <stdint.h>

#define B 4
#define T 2048
#define C 1024
#define H 16
#define D 64
#define BT (B*T)
#define SCALE 0.125f

typedef __nv_bfloat16 bf16;

// ---------------- scratch (__device__ globals; no allocs allowed) ----------
__device__ bf16 g_qh[(size_t)BT*C], g_ql[(size_t)BT*C];
__device__ bf16 g_kh[(size_t)BT*C], g_kl[(size_t)BT*C];
__device__ bf16 g_vh[(size_t)BT*C], g_vl[(size_t)BT*C];
__device__ bf16 g_ah[(size_t)BT*C], g_al[(size_t)BT*C];
__device__ float g_psum[(size_t)B*H*T*16];     // per-row, per-ktile partial sums of exp(s)

// ---------------- helpers ---------------------------------------------------
__device__ __forceinline__ uint32_t smem_u32(const void* p) {
    uint32_t a;
    asm("{ .reg .u64 t; cvta.to.shared.u64 t, %1; cvt.u32.u64 %0, t; }" : "=r"(a) : "l"(p));
    return a;
}
__device__ __forceinline__ void ldsm4(uint32_t a, uint32_t r[4]) {
    asm volatile("ldmatrix.sync.aligned.m8n8.x4.shared.b16 {%0,%1,%2,%3}, [%4];"
                 : "=r"(r[0]), "=r"(r[1]), "=r"(r[2]), "=r"(r[3]) : "r"(a));
}
__device__ __forceinline__ void ldsm2(uint32_t a, uint32_t r[2]) {
    asm volatile("ldmatrix.sync.aligned.m8n8.x2.shared.b16 {%0,%1}, [%2];"
                 : "=r"(r[0]), "=r"(r[1]) : "r"(a));
}
__device__ __forceinline__ void ldsm2t(uint32_t a, uint32_t r[2]) {
    asm volatile("ldmatrix.sync.aligned.m8n8.x2.trans.shared.b16 {%0,%1}, [%2];"
                 : "=r"(r[0]), "=r"(r[1]) : "r"(a));
}
__device__ __forceinline__ void mma_bf16(float c[4], const uint32_t a[4], const uint32_t b2[2]) {
    asm volatile("mma.sync.aligned.m16n8k16.row.col.f32.bf16.bf16.f32 "
                 "{%0,%1,%2,%3}, {%4,%5,%6,%7}, {%8,%9}, {%0,%1,%2,%3};"
                 : "+f"(c[0]), "+f"(c[1]), "+f"(c[2]), "+f"(c[3])
                 : "r"(a[0]), "r"(a[1]), "r"(a[2]), "r"(a[3]), "r"(b2[0]), "r"(b2[1]));
}
__device__ __forceinline__ uint32_t pack2(bf16 a, bf16 b) {
    __nv_bfloat162 t = __halves2bfloat162(a, b);
    return *(uint32_t*)&t;
}
__device__ __forceinline__ void fsplit(float v, bf16& h, bf16& l) {
    h = __float2bfloat16(v);
    l = __float2bfloat16(v - __bfloat162float(h));
}
__device__ __forceinline__ void stage16_f32(const float* src, bf16* dh, bf16* dl) {
#pragma unroll
    for (int j = 0; j < 16; j += 4) {
        float4 v = *(const float4*)(src + j);
        bf16 h0,h1,h2,h3,l0,l1,l2,l3;
        fsplit(v.x,h0,l0); fsplit(v.y,h1,l1); fsplit(v.z,h2,l2); fsplit(v.w,h3,l3);
        *(uint2*)(dh + j) = make_uint2(pack2(h0,h1), pack2(h2,h3));
        *(uint2*)(dl + j) = make_uint2(pack2(l0,l1), pack2(l2,l3));
    }
}
// stage 16 probs: read e, normalize, write p back to global, split into smem
__device__ __forceinline__ void stage16_norm(float* gptr, float inv, bf16* dh, bf16* dl) {
#pragma unroll
    for (int j = 0; j < 16; j += 4) {
        float4 v = *(const float4*)(gptr + j);
        v.x *= inv; v.y *= inv; v.z *= inv; v.w *= inv;
        *(float4*)(gptr + j) = v;
        bf16 h0,h1,h2,h3,l0,l1,l2,l3;
        fsplit(v.x,h0,l0); fsplit(v.y,h1,l1); fsplit(v.z,h2,l2); fsplit(v.w,h3,l3);
        *(uint2*)(dh + j) = make_uint2(pack2(h0,h1), pack2(h2,h3));
        *(uint2*)(dl + j) = make_uint2(pack2(l0,l1), pack2(l2,l3));
    }
}

// ---------------------------------------------------------------------------
// Projection GEMM on tensor cores: out[M=BT,N=C] = (X @ W^T + bias) * scale
// MODE 0: X fp32 -> write split bf16 (outh/outl).  MODE 1: X split -> fp32 out.
// ---------------------------------------------------------------------------
#define PROJ_SMEM (8 * 5120 * 2)

template<int MODE>
__global__ __launch_bounds__(256, 1)
void proj_tc(const float* __restrict__ Xf,
             const bf16* __restrict__ Xh, const bf16* __restrict__ Xl,
             const float* __restrict__ W, const float* __restrict__ bias,
             float scale,
             float* __restrict__ outf, bf16* __restrict__ outh, bf16* __restrict__ outl) {
    extern __shared__ char smc[];
    bf16* sAh = (bf16*)smc;          // [2][128*40]
    bf16* sAl = sAh + 2 * 5120;
    bf16* sBh = sAl + 2 * 5120;
    bf16* sBl = sBh + 2 * 5120;

    const int tid = threadIdx.x;
    const int wid = tid >> 5, lane = tid & 31;
    const int bm = blockIdx.y * 128, bn = blockIdx.x * 128;
    const int wm = (wid >> 2) * 64, wn = (wid & 3) * 32;
    const int srow = tid >> 1, scb = (tid & 1) * 16;

    float acc[4][4][4] = {};

    {
        bf16* dh = sAh + srow * 40 + scb;
        bf16* dl = sAl + srow * 40 + scb;
        if (MODE == 0) {
            stage16_f32(Xf + (size_t)(bm + srow) * C + scb, dh, dl);
        } else {
            const bf16* xh = Xh + (size_t)(bm + srow) * C + scb;
            const bf16* xl = Xl + (size_t)(bm + srow) * C + scb;
            *(uint4*)dh = *(const uint4*)xh; *(uint4*)(dh + 8) = *(const uint4*)(xh + 8);
            *(uint4*)dl = *(const uint4*)xl; *(uint4*)(dl + 8) = *(const uint4*)(xl + 8);
        }
        stage16_f32(W + (size_t)(bn + srow) * C + scb, sBh + srow * 40 + scb, sBl + srow * 40 + scb);
    }
    __syncthreads();

    for (int c = 0; c < 32; c++) {
        const int buf = c & 1;
        if (c + 1 < 32) {
            const int k0 = (c + 1) * 32;
            const int nb = buf ^ 1;
            bf16* dh = sAh + nb * 5120 + srow * 40 + scb;
            bf16* dl = sAl + nb * 5120 + srow * 40 + scb;
            if (MODE == 0) {
                stage16_f32(Xf + (size_t)(bm + srow) * C + k0 + scb, dh, dl);
            } else {
                const bf16* xh = Xh + (size_t)(bm + srow) * C + k0 + scb;
                const bf16* xl = Xl + (size_t)(bm + srow) * C + k0 + scb;
                *(uint4*)dh = *(const uint4*)xh; *(uint4*)(dh + 8) = *(const uint4*)(xh + 8);
                *(uint4*)dl = *(const uint4*)xl; *(uint4*)(dl + 8) = *(const uint4*)(xl + 8);
            }
            stage16_f32(W + (size_t)(bn + srow) * C + k0 + scb,
                        sBh + nb * 5120 + srow * 40 + scb, sBl + nb * 5120 + srow * 40 + scb);
        }
        const uint32_t bAh = smem_u32(sAh + buf * 5120);
        const uint32_t bAl = smem_u32(sAl + buf * 5120);
        const uint32_t bBh = smem_u32(sBh + buf * 5120);
        const uint32_t bBl = smem_u32(sBl + buf * 5120);
#pragma unroll
        for (int s = 0; s < 2; s++) {
            uint32_t afh[4][4], afl[4][4], fbh[4][2], fbl[4][2];
#pragma unroll
            for (int mf = 0; mf < 4; mf++) {
                uint32_t off = (uint32_t)(wm + mf * 16 + (lane & 15)) * 80 + s * 32 + ((lane >> 4) * 16);
                ldsm4(bAh + off, afh[mf]);
                ldsm4(bAl + off, afl[mf]);
            }
#pragma unroll
            for (int nf = 0; nf < 4; nf++) {
                uint32_t off = (uint32_t)(wn + nf * 8 + (lane & 7)) * 80 + s * 32 + (((lane >> 3) & 1) * 16);
                ldsm2(bBh + off, fbh[nf]);
                ldsm2(bBl + off, fbl[nf]);
            }
#pragma unroll
            for (int mf = 0; mf < 4; mf++)
#pragma unroll
                for (int nf = 0; nf < 4; nf++) {
                    mma_bf16(acc[mf][nf], afh[mf], fbh[nf]);
                    mma_bf16(acc[mf][nf], afh[mf], fbl[nf]);
                    mma_bf16(acc[mf][nf], afl[mf], fbh[nf]);
                }
        }
        __syncthreads();
    }

#pragma unroll
    for (int mf = 0; mf < 4; mf++) {
        const int gr = bm + wm + mf * 16 + (lane >> 2);
#pragma unroll
        for (int nf = 0; nf < 4; nf++) {
            const int gc = bn + wn + nf * 8 + (lane & 3) * 2;
            float b0 = bias[gc], b1 = bias[gc + 1];
            float v0 = (acc[mf][nf][0] + b0) * scale;
            float v1 = (acc[mf][nf][1] + b1) * scale;
            float v2 = (acc[mf][nf][2] + b0) * scale;
            float v3 = (acc[mf][nf][3] + b1) * scale;
            if (MODE == 0) {
                bf16 h0,h1,l0,l1; fsplit(v0,h0,l0); fsplit(v1,h1,l1);
                *(uint32_t*)(outh + (size_t)gr * C + gc) = pack2(h0, h1);
                *(uint32_t*)(outl + (size_t)gr * C + gc) = pack2(l0, l1);
                fsplit(v2,h0,l0); fsplit(v3,h1,l1);
                *(uint32_t*)(outh + (size_t)(gr + 8) * C + gc) = pack2(h0, h1);
                *(uint32_t*)(outl + (size_t)(gr + 8) * C + gc) = pack2(l0, l1);
            } else {
                *(float2*)(outf + (size_t)gr * C + gc)       = make_float2(v0, v1);
                *(float2*)(outf + (size_t)(gr + 8) * C + gc) = make_float2(v2, v3);
            }
        }
    }
}

// ---------------------------------------------------------------------------
// Scores+exp: e = exp(Q.K^T) masked (causal + key padding); writes e to attn,
// per-row partial sums to g_psum[bh][row][kt]. Lower-triangle tiles only.
// ---------------------------------------------------------------------------
#define SCORES_SMEM (4 * 9216 * 2)

__global__ __launch_bounds__(256, 1)
void scores_tc(const bf16* __restrict__ qh, const bf16* __restrict__ ql,
               const bf16* __restrict__ kh, const bf16* __restrict__ kl,
               const unsigned char* __restrict__ kp, float* __restrict__ attn,
               float* __restrict__ psum) {
    const int kt = blockIdx.x, qt = blockIdx.y, bh = blockIdx.z;
    if (kt > qt) return;
    const int b = bh >> 4, h = bh & 15;

    extern __shared__ char smc[];
    bf16* sQh = (bf16*)smc;          // [128*72]
    bf16* sQl = sQh + 9216;
    bf16* sKh = sQl + 9216;
    bf16* sKl = sKh + 9216;
    __shared__ float sred[4][128];

    const int tid = threadIdx.x;
    const int wid = tid >> 5, lane = tid & 31;
    const int wm = (wid >> 2) * 64, wn = (wid & 3) * 32;
    const int srow = tid >> 1, scb = (tid & 1) * 32;

    {
        const size_t qoff = (size_t)(b * T + qt * 128 + srow) * C + h * 64 + scb;
        const size_t koff = (size_t)(b * T + kt * 128 + srow) * C + h * 64 + scb;
        bf16* d;
        d = sQh + srow * 72 + scb;
#pragma unroll
        for (int j = 0; j < 32; j += 8) *(uint4*)(d + j) = *(const uint4*)(qh + qoff + j);
        d = sQl + srow * 72 + scb;
#pragma unroll
        for (int j = 0; j < 32; j += 8) *(uint4*)(d + j) = *(const uint4*)(ql + qoff + j);
        d = sKh + srow * 72 + scb;
#pragma unroll
        for (int j = 0; j < 32; j += 8) *(uint4*)(d + j) = *(const uint4*)(kh + koff + j);
        d = sKl + srow * 72 + scb;
#pragma unroll
        for (int j = 0; j < 32; j += 8) *(uint4*)(d + j) = *(const uint4*)(kl + koff + j);
    }
    __syncthreads();

    float acc[4][4][4] = {};
    const uint32_t bQh = smem_u32(sQh), bQl = smem_u32(sQl);
    const uint32_t bKh = smem_u32(sKh), bKl = smem_u32(sKl);

#pragma unroll
    for (int s = 0; s < 4; s++) {
        uint32_t afh[4][4], afl[4][4], fbh[4][2], fbl[4][2];
#pragma unroll
        for (int mf = 0; mf < 4; mf++) {
            uint32_t off = (uint32_t)(wm + mf * 16 + (lane & 15)) * 144 + s * 32 + ((lane >> 4) * 16);
            ldsm4(bQh + off, afh[mf]);
            ldsm4(bQl + off, afl[mf]);
        }
#pragma unroll
        for (int nf = 0; nf < 4; nf++) {
            uint32_t off = (uint32_t)(wn + nf * 8 + (lane & 7)) * 144 + s * 32 + (((lane >> 3) & 1) * 16);
            ldsm2(bKh + off, fbh[nf]);
            ldsm2(bKl + off, fbl[nf]);
        }
#pragma unroll
        for (int mf = 0; mf < 4; mf++)
#pragma unroll
            for (int nf = 0; nf < 4; nf++) {
                mma_bf16(acc[mf][nf], afh[mf], fbh[nf]);
                mma_bf16(acc[mf][nf], afh[mf], fbl[nf]);
                mma_bf16(acc[mf][nf], afl[mf], fbh[nf]);
            }
    }

    // per-column key-padding flags (same cols for all mf)
    float kpc[8];
#pragma unroll
    for (int nf = 0; nf < 4; nf++) {
        const int gc = kt * 128 + wn + nf * 8 + (lane & 3) * 2;
        kpc[nf*2]   = kp[b * T + gc]     ? 0.f : 1.f;
        kpc[nf*2+1] = kp[b * T + gc + 1] ? 0.f : 1.f;
    }

    float* ab = attn + (size_t)bh * T * T;
#pragma unroll
    for (int mf = 0; mf < 4; mf++) {
        const int lr0 = wm + mf * 16 + (lane >> 2);   // local row
        const int gr0 = qt * 128 + lr0;
        const int gr1 = gr0 + 8;
        float rs0 = 0.f, rs1 = 0.f;
#pragma unroll
        for (int nf = 0; nf < 4; nf++) {
            const int gc = kt * 128 + wn + nf * 8 + (lane & 3) * 2;
            float e0 = (gc     <= gr0) ? kpc[nf*2]   * __expf(acc[mf][nf][0]) : 0.f;
            float e1 = (gc + 1 <= gr0) ? kpc[nf*2+1] * __expf(acc[mf][nf][1]) : 0.f;
            float e2 = (gc     <= gr1) ? kpc[nf*2]   * __expf(acc[mf][nf][2]) : 0.f;
            float e3 = (gc + 1 <= gr1) ? kpc[nf*2+1] * __expf(acc[mf][nf][3]) : 0.f;
            rs0 += e0 + e1; rs1 += e2 + e3;
            *(float2*)(ab + (size_t)gr0 * T + gc) = make_float2(e0, e1);
            *(float2*)(ab + (size_t)gr1 * T + gc) = make_float2(e2, e3);
        }
        // reduce across the 4 lanes holding this row (lane&3 varies)
        rs0 += __shfl_xor_sync(0xffffffff, rs0, 1);
        rs0 += __shfl_xor_sync(0xffffffff, rs0, 2);
        rs1 += __shfl_xor_sync(0xffffffff, rs1, 1);
        rs1 += __shfl_xor_sync(0xffffffff, rs1, 2);
        if ((lane & 3) == 0) {
            sred[wid & 3][lr0]     = rs0;
            sred[wid & 3][lr0 + 8] = rs1;
        }
    }
    __syncthreads();
    if (tid < 128) {
        float s = sred[0][tid] + sred[1][tid] + sred[2][tid] + sred[3][tid];
        psum[((size_t)bh * T + qt * 128 + tid) * 16 + kt] = s;
    }
}

// ---------------------------------------------------------------------------
// Zero-fill strictly-upper 128x128 tiles of attn (poisoned output buffer).
// ---------------------------------------------------------------------------
__global__ void zfill(float* __restrict__ attn) {
    const int qt = blockIdx.x >> 4, kt = blockIdx.x & 15;
    if (kt <= qt) return;
    const int bh = blockIdx.y;
    float* base = attn + (size_t)bh * T * T + (size_t)(qt * 128) * T + kt * 128;
    const float4 z = {0.f, 0.f, 0.f, 0.f};
    for (int i = threadIdx.x; i < 128 * 32; i += 256) {
        int row = i >> 5, c4 = (i & 31) * 4;
        *(float4*)(base + (size_t)row * T + c4) = z;
    }
}

// ---------------------------------------------------------------------------
// AV + normalize: inv[row] from psum; stream e-tiles, write p = e*inv back,
// accumulate O = P @ V with normalized p. Output split bf16 for Wo GEMM.
// ---------------------------------------------------------------------------
#define AV_SMEM ((2 * 5120 + 2 * 2304) * 2)

__global__ __launch_bounds__(256, 1)
void av_tc(float* __restrict__ attn, const float* __restrict__ psum,
           const bf16* __restrict__ vh, const bf16* __restrict__ vl,
           bf16* __restrict__ outh, bf16* __restrict__ outl) {
    const int qt = blockIdx.x, bh = blockIdx.y;
    const int b = bh >> 4, h = bh & 15;

    extern __shared__ char smc[];
    bf16* sPh = (bf16*)smc;          // [128*40]
    bf16* sPl = sPh + 5120;
    bf16* sVh = sPl + 5120;          // [32*72]
    bf16* sVl = sVh + 2304;
    __shared__ float sinv[128];

    const int tid = threadIdx.x;
    const int wid = tid >> 5, lane = tid & 31;
    const int wm = (wid >> 2) * 64, wn = (wid & 3) * 16;
    const int prow = tid >> 1, pcb = (tid & 1) * 16;
    const int vrow = tid >> 3, vcb = (tid & 7) * 8;

    if (tid < 128) {
        const float* ps = psum + ((size_t)bh * T + qt * 128 + tid) * 16;
        float s = 0.f;
        for (int k = 0; k <= qt; k++) s += ps[k];
        sinv[tid] = 1.0f / s;
    }
    __syncthreads();

    float acc[4][2][4] = {};
    const int nkt = 4 * qt + 4;
    const float pinv = sinv[prow];

    const uint32_t bPh = smem_u32(sPh), bPl = smem_u32(sPl);
    const uint32_t bVh = smem_u32(sVh), bVl = smem_u32(sVl);

    for (int kt = 0; kt < nkt; kt++) {
        const int t0 = kt * 32;
        stage16_norm(attn + (size_t)bh * T * T + (size_t)(qt * 128 + prow) * T + t0 + pcb,
                     pinv, sPh + prow * 40 + pcb, sPl + prow * 40 + pcb);
        {
            const size_t voff = (size_t)(b * T + t0 + vrow) * C + h * 64 + vcb;
            *(uint4*)(sVh + vrow * 72 + vcb) = *(const uint4*)(vh + voff);
            *(uint4*)(sVl + vrow * 72 + vcb) = *(const uint4*)(vl + voff);
        }
        __syncthreads();

#pragma unroll
        for (int s = 0; s < 2; s++) {
            uint32_t afh[4][4], afl[4][4], fbh[2][2], fbl[2][2];
#pragma unroll
            for (int mf = 0; mf < 4; mf++) {
                uint32_t off = (uint32_t)(wm + mf * 16 + (lane & 15)) * 80 + s * 32 + ((lane >> 4) * 16);
                ldsm4(bPh + off, afh[mf]);
                ldsm4(bPl + off, afl[mf]);
            }
#pragma unroll
            for (int nf = 0; nf < 2; nf++) {
                uint32_t off = (uint32_t)(s * 16 + (lane & 15)) * 144 + (wn + nf * 8) * 2;
                ldsm2t(bVh + off, fbh[nf]);
                ldsm2t(bVl + off, fbl[nf]);
            }
#pragma unroll
            for (int mf = 0; mf < 4; mf++)
#pragma unroll
                for (int nf = 0; nf < 2; nf++) {
                    mma_bf16(acc[mf][nf], afh[mf], fbh[nf]);
                    mma_bf16(acc[mf][nf], afh[mf], fbl[nf]);
                    mma_bf16(acc[mf][nf], afl[mf], fbh[nf]);
                }
        }
        __syncthreads();
    }

#pragma unroll
    for (int mf = 0; mf < 4; mf++) {
        const int gr = b * T + qt * 128 + wm + mf * 16 + (lane >> 2);
#pragma unroll
        for (int nf = 0; nf < 2; nf++) {
            const int gc = h * 64 + wn + nf * 8 + (lane & 3) * 2;
            bf16 h0,h1,l0,l1;
            fsplit(acc[mf][nf][0], h0, l0); fsplit(acc[mf][nf][1], h1, l1);
            *(uint32_t*)(outh + (size_t)gr * C + gc) = pack2(h0, h1);
            *(uint32_t*)(outl + (size_t)gr * C + gc) = pack2(l0, l1);
            fsplit(acc[mf][nf][2], h0, l0); fsplit(acc[mf][nf][3], h1, l1);
            *(uint32_t*)(outh + (size_t)(gr + 8) * C + gc) = pack2(h0, h1);
            *(uint32_t*)(outl + (size_t)(gr + 8) * C + gc) = pack2(l0, l1);
        }
    }
}

// ---------------------------------------------------------------------------
extern "C" void kernel_launch(void* const* d_in, const int* in_sizes, int n_in,
                              void* d_out, int out_size) {
    const float* query = (const float*)d_in[0];
    const float* key   = (const float*)d_in[1];
    const float* value = (const float*)d_in[2];
    const unsigned char* kp = (const unsigned char*)d_in[4];
    const float* Wq = (const float*)d_in[5];  const float* bq = (const float*)d_in[6];
    const float* Wk = (const float*)d_in[7];  const float* bk = (const float*)d_in[8];
    const float* Wv = (const float*)d_in[9];  const float* bv = (const float*)d_in[10];
    const float* Wo = (const float*)d_in[11]; const float* bo = (const float*)d_in[12];

    float* y    = (float*)d_out;
    float* attn = y + (size_t)BT * C;   // tuple order: (y, attn_weights)

    bf16 *qh,*ql,*kh,*kl,*vh,*vl,*ah,*al;
    float* psum;
    cudaGetSymbolAddress((void**)&qh, g_qh); cudaGetSymbolAddress((void**)&ql, g_ql);
    cudaGetSymbolAddress((void**)&kh, g_kh); cudaGetSymbolAddress((void**)&kl, g_kl);
    cudaGetSymbolAddress((void**)&vh, g_vh); cudaGetSymbolAddress((void**)&vl, g_vl);
    cudaGetSymbolAddress((void**)&ah, g_ah); cudaGetSymbolAddress((void**)&al, g_al);
    cudaGetSymbolAddress((void**)&psum, g_psum);

    cudaFuncSetAttribute(proj_tc<0>, cudaFuncAttributeMaxDynamicSharedMemorySize, PROJ_SMEM);
    cudaFuncSetAttribute(proj_tc<1>, cudaFuncAttributeMaxDynamicSharedMemorySize, PROJ_SMEM);
    cudaFuncSetAttribute(scores_tc,  cudaFuncAttributeMaxDynamicSharedMemorySize, SCORES_SMEM);

    dim3 pg(C / 128, BT / 128);   // (8, 64)

    // projections (SCALE folded into Q)
    proj_tc<0><<<pg, 256, PROJ_SMEM>>>(query, nullptr, nullptr, Wq, bq, SCALE, nullptr, qh, ql);
    proj_tc<0><<<pg, 256, PROJ_SMEM>>>(key,   nullptr, nullptr, Wk, bk, 1.0f,  nullptr, kh, kl);
    proj_tc<0><<<pg, 256, PROJ_SMEM>>>(value, nullptr, nullptr, Wv, bv, 1.0f,  nullptr, vh, vl);

    // zero strictly-upper tiles (independent of scores)
    dim3 zg(256, B * H);
    zfill<<<zg, 256>>>(attn);

    // scores + exp + row partial sums (lower-triangle tiles)
    dim3 sg(T / 128, T / 128, B * H);
    scores_tc<<<sg, 256, SCORES_SMEM>>>(qh, ql, kh, kl, kp, attn, psum);

    // AV + in-place normalization of attn
    dim3 ag(T / 128, B * H);
    av_tc<<<ag, 256, AV_SMEM>>>(attn, psum, vh, vl, ah, al);

    // output projection
    proj_tc<1><<<pg, 256, PROJ_SMEM>>>(nullptr, ah, al, Wo, bo, 1.0f, y, nullptr, nullptr);
}

// round 7
// speedup vs baseline: 1.8204x; 1.2414x over previous
#include <cuda_runtime.h>
#include <cuda_bf16.h>
#include <math.h>
#include <stdint.h>

#define B 4
#define T 2048
#define C 1024
#define H 16
#define D 64
#define BT (B*T)
#define SCALE 0.125f

typedef __nv_bfloat16 bf16;

// ---------------- scratch (__device__ globals; no allocs allowed) ----------
__device__ bf16 g_qh[(size_t)BT*C], g_ql[(size_t)BT*C];
__device__ bf16 g_kh[(size_t)BT*C], g_kl[(size_t)BT*C];
__device__ bf16 g_vh[(size_t)BT*C], g_vl[(size_t)BT*C];
__device__ bf16 g_ah[(size_t)BT*C], g_al[(size_t)BT*C];
__device__ float g_psum[(size_t)B*H*T*16];     // per-row, per-ktile partial sums of exp(s)

// ---------------- helpers ---------------------------------------------------
__device__ __forceinline__ uint32_t smem_u32(const void* p) {
    uint32_t a;
    asm("{ .reg .u64 t; cvta.to.shared.u64 t, %1; cvt.u32.u64 %0, t; }" : "=r"(a) : "l"(p));
    return a;
}
__device__ __forceinline__ void ldsm4(uint32_t a, uint32_t r[4]) {
    asm volatile("ldmatrix.sync.aligned.m8n8.x4.shared.b16 {%0,%1,%2,%3}, [%4];"
                 : "=r"(r[0]), "=r"(r[1]), "=r"(r[2]), "=r"(r[3]) : "r"(a));
}
__device__ __forceinline__ void ldsm2(uint32_t a, uint32_t r[2]) {
    asm volatile("ldmatrix.sync.aligned.m8n8.x2.shared.b16 {%0,%1}, [%2];"
                 : "=r"(r[0]), "=r"(r[1]) : "r"(a));
}
__device__ __forceinline__ void ldsm2t(uint32_t a, uint32_t r[2]) {
    asm volatile("ldmatrix.sync.aligned.m8n8.x2.trans.shared.b16 {%0,%1}, [%2];"
                 : "=r"(r[0]), "=r"(r[1]) : "r"(a));
}
__device__ __forceinline__ void mma_bf16(float c[4], const uint32_t a[4], const uint32_t b2[2]) {
    asm volatile("mma.sync.aligned.m16n8k16.row.col.f32.bf16.bf16.f32 "
                 "{%0,%1,%2,%3}, {%4,%5,%6,%7}, {%8,%9}, {%0,%1,%2,%3};"
                 : "+f"(c[0]), "+f"(c[1]), "+f"(c[2]), "+f"(c[3])
                 : "r"(a[0]), "r"(a[1]), "r"(a[2]), "r"(a[3]), "r"(b2[0]), "r"(b2[1]));
}
__device__ __forceinline__ uint32_t pack2(bf16 a, bf16 b) {
    __nv_bfloat162 t = __halves2bfloat162(a, b);
    return *(uint32_t*)&t;
}
__device__ __forceinline__ void fsplit(float v, bf16& h, bf16& l) {
    h = __float2bfloat16(v);
    l = __float2bfloat16(v - __bfloat162float(h));
}
__device__ __forceinline__ void stage16_f32(const float* src, bf16* dh, bf16* dl) {
#pragma unroll
    for (int j = 0; j < 16; j += 4) {
        float4 v = *(const float4*)(src + j);
        bf16 h0,h1,h2,h3,l0,l1,l2,l3;
        fsplit(v.x,h0,l0); fsplit(v.y,h1,l1); fsplit(v.z,h2,l2); fsplit(v.w,h3,l3);
        *(uint2*)(dh + j) = make_uint2(pack2(h0,h1), pack2(h2,h3));
        *(uint2*)(dl + j) = make_uint2(pack2(l0,l1), pack2(l2,l3));
    }
}
// stage 16 probs: read e, normalize, write p back to global, split into smem
__device__ __forceinline__ void stage16_norm(float* gptr, float inv, bf16* dh, bf16* dl) {
#pragma unroll
    for (int j = 0; j < 16; j += 4) {
        float4 v = *(const float4*)(gptr + j);
        v.x *= inv; v.y *= inv; v.z *= inv; v.w *= inv;
        *(float4*)(gptr + j) = v;
        bf16 h0,h1,h2,h3,l0,l1,l2,l3;
        fsplit(v.x,h0,l0); fsplit(v.y,h1,l1); fsplit(v.z,h2,l2); fsplit(v.w,h3,l3);
        *(uint2*)(dh + j) = make_uint2(pack2(h0,h1), pack2(h2,h3));
        *(uint2*)(dl + j) = make_uint2(pack2(l0,l1), pack2(l2,l3));
    }
}

// ---------------------------------------------------------------------------
// Projection GEMM on tensor cores: out[M=BT,N=C] = (X @ W^T + bias) * scale
// MODE 0: X fp32 -> write split bf16 (outh/outl).  MODE 1: X split -> fp32 out.
// 2 CTAs/SM (regs capped at 128) so staging of one CTA hides MMA of the other.
// ---------------------------------------------------------------------------
#define PROJ_SMEM (8 * 5120 * 2)

template<int MODE>
__global__ __launch_bounds__(256, 2)
void proj_tc(const float* __restrict__ Xf,
             const bf16* __restrict__ Xh, const bf16* __restrict__ Xl,
             const float* __restrict__ W, const float* __restrict__ bias,
             float scale,
             float* __restrict__ outf, bf16* __restrict__ outh, bf16* __restrict__ outl) {
    extern __shared__ char smc[];
    bf16* sAh = (bf16*)smc;          // [2][128*40]
    bf16* sAl = sAh + 2 * 5120;
    bf16* sBh = sAl + 2 * 5120;
    bf16* sBl = sBh + 2 * 5120;

    const int tid = threadIdx.x;
    const int wid = tid >> 5, lane = tid & 31;
    const int bm = blockIdx.y * 128, bn = blockIdx.x * 128;
    const int wm = (wid >> 2) * 64, wn = (wid & 3) * 32;
    const int srow = tid >> 1, scb = (tid & 1) * 16;

    float acc[4][4][4] = {};

    {
        bf16* dh = sAh + srow * 40 + scb;
        bf16* dl = sAl + srow * 40 + scb;
        if (MODE == 0) {
            stage16_f32(Xf + (size_t)(bm + srow) * C + scb, dh, dl);
        } else {
            const bf16* xh = Xh + (size_t)(bm + srow) * C + scb;
            const bf16* xl = Xl + (size_t)(bm + srow) * C + scb;
            *(uint4*)dh = *(const uint4*)xh; *(uint4*)(dh + 8) = *(const uint4*)(xh + 8);
            *(uint4*)dl = *(const uint4*)xl; *(uint4*)(dl + 8) = *(const uint4*)(xl + 8);
        }
        stage16_f32(W + (size_t)(bn + srow) * C + scb, sBh + srow * 40 + scb, sBl + srow * 40 + scb);
    }
    __syncthreads();

    for (int c = 0; c < 32; c++) {
        const int buf = c & 1;
        if (c + 1 < 32) {
            const int k0 = (c + 1) * 32;
            const int nb = buf ^ 1;
            bf16* dh = sAh + nb * 5120 + srow * 40 + scb;
            bf16* dl = sAl + nb * 5120 + srow * 40 + scb;
            if (MODE == 0) {
                stage16_f32(Xf + (size_t)(bm + srow) * C + k0 + scb, dh, dl);
            } else {
                const bf16* xh = Xh + (size_t)(bm + srow) * C + k0 + scb;
                const bf16* xl = Xl + (size_t)(bm + srow) * C + k0 + scb;
                *(uint4*)dh = *(const uint4*)xh; *(uint4*)(dh + 8) = *(const uint4*)(xh + 8);
                *(uint4*)dl = *(const uint4*)xl; *(uint4*)(dl + 8) = *(const uint4*)(xl + 8);
            }
            stage16_f32(W + (size_t)(bn + srow) * C + k0 + scb,
                        sBh + nb * 5120 + srow * 40 + scb, sBl + nb * 5120 + srow * 40 + scb);
        }
        const uint32_t bAh = smem_u32(sAh + buf * 5120);
        const uint32_t bAl = smem_u32(sAl + buf * 5120);
        const uint32_t bBh = smem_u32(sBh + buf * 5120);
        const uint32_t bBl = smem_u32(sBl + buf * 5120);
#pragma unroll
        for (int s = 0; s < 2; s++) {
            uint32_t afh[4][4], afl[4][4], fbh[4][2], fbl[4][2];
#pragma unroll
            for (int mf = 0; mf < 4; mf++) {
                uint32_t off = (uint32_t)(wm + mf * 16 + (lane & 15)) * 80 + s * 32 + ((lane >> 4) * 16);
                ldsm4(bAh + off, afh[mf]);
                ldsm4(bAl + off, afl[mf]);
            }
#pragma unroll
            for (int nf = 0; nf < 4; nf++) {
                uint32_t off = (uint32_t)(wn + nf * 8 + (lane & 7)) * 80 + s * 32 + (((lane >> 3) & 1) * 16);
                ldsm2(bBh + off, fbh[nf]);
                ldsm2(bBl + off, fbl[nf]);
            }
#pragma unroll
            for (int mf = 0; mf < 4; mf++)
#pragma unroll
                for (int nf = 0; nf < 4; nf++) {
                    mma_bf16(acc[mf][nf], afh[mf], fbh[nf]);
                    mma_bf16(acc[mf][nf], afh[mf], fbl[nf]);
                    mma_bf16(acc[mf][nf], afl[mf], fbh[nf]);
                }
        }
        __syncthreads();
    }

#pragma unroll
    for (int mf = 0; mf < 4; mf++) {
        const int gr = bm + wm + mf * 16 + (lane >> 2);
#pragma unroll
        for (int nf = 0; nf < 4; nf++) {
            const int gc = bn + wn + nf * 8 + (lane & 3) * 2;
            float b0 = bias[gc], b1 = bias[gc + 1];
            float v0 = (acc[mf][nf][0] + b0) * scale;
            float v1 = (acc[mf][nf][1] + b1) * scale;
            float v2 = (acc[mf][nf][2] + b0) * scale;
            float v3 = (acc[mf][nf][3] + b1) * scale;
            if (MODE == 0) {
                bf16 h0,h1,l0,l1; fsplit(v0,h0,l0); fsplit(v1,h1,l1);
                *(uint32_t*)(outh + (size_t)gr * C + gc) = pack2(h0, h1);
                *(uint32_t*)(outl + (size_t)gr * C + gc) = pack2(l0, l1);
                fsplit(v2,h0,l0); fsplit(v3,h1,l1);
                *(uint32_t*)(outh + (size_t)(gr + 8) * C + gc) = pack2(h0, h1);
                *(uint32_t*)(outl + (size_t)(gr + 8) * C + gc) = pack2(l0, l1);
            } else {
                *(float2*)(outf + (size_t)gr * C + gc)       = make_float2(v0, v1);
                *(float2*)(outf + (size_t)(gr + 8) * C + gc) = make_float2(v2, v3);
            }
        }
    }
}

// ---------------------------------------------------------------------------
// Scores+exp: e = exp(Q.K^T) masked (causal + key padding); writes e to attn,
// per-row partial sums to g_psum[bh][row][kt]. Lower-triangle tiles only.
// 2 CTAs/SM.
// ---------------------------------------------------------------------------
#define SCORES_SMEM (4 * 9216 * 2)

__global__ __launch_bounds__(256, 2)
void scores_tc(const bf16* __restrict__ qh, const bf16* __restrict__ ql,
               const bf16* __restrict__ kh, const bf16* __restrict__ kl,
               const unsigned char* __restrict__ kp, float* __restrict__ attn,
               float* __restrict__ psum) {
    const int kt = blockIdx.x, qt = blockIdx.y, bh = blockIdx.z;
    if (kt > qt) return;
    const int b = bh >> 4, h = bh & 15;

    extern __shared__ char smc[];
    bf16* sQh = (bf16*)smc;          // [128*72]
    bf16* sQl = sQh + 9216;
    bf16* sKh = sQl + 9216;
    bf16* sKl = sKh + 9216;
    __shared__ float sred[4][128];

    const int tid = threadIdx.x;
    const int wid = tid >> 5, lane = tid & 31;
    const int wm = (wid >> 2) * 64, wn = (wid & 3) * 32;
    const int srow = tid >> 1, scb = (tid & 1) * 32;

    {
        const size_t qoff = (size_t)(b * T + qt * 128 + srow) * C + h * 64 + scb;
        const size_t koff = (size_t)(b * T + kt * 128 + srow) * C + h * 64 + scb;
        bf16* d;
        d = sQh + srow * 72 + scb;
#pragma unroll
        for (int j = 0; j < 32; j += 8) *(uint4*)(d + j) = *(const uint4*)(qh + qoff + j);
        d = sQl + srow * 72 + scb;
#pragma unroll
        for (int j = 0; j < 32; j += 8) *(uint4*)(d + j) = *(const uint4*)(ql + qoff + j);
        d = sKh + srow * 72 + scb;
#pragma unroll
        for (int j = 0; j < 32; j += 8) *(uint4*)(d + j) = *(const uint4*)(kh + koff + j);
        d = sKl + srow * 72 + scb;
#pragma unroll
        for (int j = 0; j < 32; j += 8) *(uint4*)(d + j) = *(const uint4*)(kl + koff + j);
    }
    __syncthreads();

    float acc[4][4][4] = {};
    const uint32_t bQh = smem_u32(sQh), bQl = smem_u32(sQl);
    const uint32_t bKh = smem_u32(sKh), bKl = smem_u32(sKl);

#pragma unroll
    for (int s = 0; s < 4; s++) {
        uint32_t afh[4][4], afl[4][4], fbh[4][2], fbl[4][2];
#pragma unroll
        for (int mf = 0; mf < 4; mf++) {
            uint32_t off = (uint32_t)(wm + mf * 16 + (lane & 15)) * 144 + s * 32 + ((lane >> 4) * 16);
            ldsm4(bQh + off, afh[mf]);
            ldsm4(bQl + off, afl[mf]);
        }
#pragma unroll
        for (int nf = 0; nf < 4; nf++) {
            uint32_t off = (uint32_t)(wn + nf * 8 + (lane & 7)) * 144 + s * 32 + (((lane >> 3) & 1) * 16);
            ldsm2(bKh + off, fbh[nf]);
            ldsm2(bKl + off, fbl[nf]);
        }
#pragma unroll
        for (int mf = 0; mf < 4; mf++)
#pragma unroll
            for (int nf = 0; nf < 4; nf++) {
                mma_bf16(acc[mf][nf], afh[mf], fbh[nf]);
                mma_bf16(acc[mf][nf], afh[mf], fbl[nf]);
                mma_bf16(acc[mf][nf], afl[mf], fbh[nf]);
            }
    }

    float kpc[8];
#pragma unroll
    for (int nf = 0; nf < 4; nf++) {
        const int gc = kt * 128 + wn + nf * 8 + (lane & 3) * 2;
        kpc[nf*2]   = kp[b * T + gc]     ? 0.f : 1.f;
        kpc[nf*2+1] = kp[b * T + gc + 1] ? 0.f : 1.f;
    }

    float* ab = attn + (size_t)bh * T * T;
#pragma unroll
    for (int mf = 0; mf < 4; mf++) {
        const int lr0 = wm + mf * 16 + (lane >> 2);
        const int gr0 = qt * 128 + lr0;
        const int gr1 = gr0 + 8;
        float rs0 = 0.f, rs1 = 0.f;
#pragma unroll
        for (int nf = 0; nf < 4; nf++) {
            const int gc = kt * 128 + wn + nf * 8 + (lane & 3) * 2;
            float e0 = (gc     <= gr0) ? kpc[nf*2]   * __expf(acc[mf][nf][0]) : 0.f;
            float e1 = (gc + 1 <= gr0) ? kpc[nf*2+1] * __expf(acc[mf][nf][1]) : 0.f;
            float e2 = (gc     <= gr1) ? kpc[nf*2]   * __expf(acc[mf][nf][2]) : 0.f;
            float e3 = (gc + 1 <= gr1) ? kpc[nf*2+1] * __expf(acc[mf][nf][3]) : 0.f;
            rs0 += e0 + e1; rs1 += e2 + e3;
            *(float2*)(ab + (size_t)gr0 * T + gc) = make_float2(e0, e1);
            *(float2*)(ab + (size_t)gr1 * T + gc) = make_float2(e2, e3);
        }
        rs0 += __shfl_xor_sync(0xffffffff, rs0, 1);
        rs0 += __shfl_xor_sync(0xffffffff, rs0, 2);
        rs1 += __shfl_xor_sync(0xffffffff, rs1, 1);
        rs1 += __shfl_xor_sync(0xffffffff, rs1, 2);
        if ((lane & 3) == 0) {
            sred[wid & 3][lr0]     = rs0;
            sred[wid & 3][lr0 + 8] = rs1;
        }
    }
    __syncthreads();
    if (tid < 128) {
        float s = sred[0][tid] + sred[1][tid] + sred[2][tid] + sred[3][tid];
        psum[((size_t)bh * T + qt * 128 + tid) * 16 + kt] = s;
    }
}

// ---------------------------------------------------------------------------
// Zero-fill strictly-upper 128x128 tiles of attn (poisoned output buffer).
// ---------------------------------------------------------------------------
__global__ void zfill(float* __restrict__ attn) {
    const int qt = blockIdx.x >> 4, kt = blockIdx.x & 15;
    if (kt <= qt) return;
    const int bh = blockIdx.y;
    float* base = attn + (size_t)bh * T * T + (size_t)(qt * 128) * T + kt * 128;
    const float4 z = {0.f, 0.f, 0.f, 0.f};
    for (int i = threadIdx.x; i < 128 * 32; i += 256) {
        int row = i >> 5, c4 = (i & 31) * 4;
        *(float4*)(base + (size_t)row * T + c4) = z;
    }
}

// ---------------------------------------------------------------------------
// AV + normalize: inv[row] from psum; stream e-tiles, write p = e*inv back,
// accumulate O = P @ V with normalized p. 2+ CTAs/SM.
// ---------------------------------------------------------------------------
#define AV_SMEM ((2 * 5120 + 2 * 2304) * 2)

__global__ __launch_bounds__(256, 2)
void av_tc(float* __restrict__ attn, const float* __restrict__ psum,
           const bf16* __restrict__ vh, const bf16* __restrict__ vl,
           bf16* __restrict__ outh, bf16* __restrict__ outl) {
    const int qt = blockIdx.x, bh = blockIdx.y;
    const int b = bh >> 4, h = bh & 15;

    extern __shared__ char smc[];
    bf16* sPh = (bf16*)smc;          // [128*40]
    bf16* sPl = sPh + 5120;
    bf16* sVh = sPl + 5120;          // [32*72]
    bf16* sVl = sVh + 2304;
    __shared__ float sinv[128];

    const int tid = threadIdx.x;
    const int wid = tid >> 5, lane = tid & 31;
    const int wm = (wid >> 2) * 64, wn = (wid & 3) * 16;
    const int prow = tid >> 1, pcb = (tid & 1) * 16;
    const int vrow = tid >> 3, vcb = (tid & 7) * 8;

    if (tid < 128) {
        const float* ps = psum + ((size_t)bh * T + qt * 128 + tid) * 16;
        float s = 0.f;
        for (int k = 0; k <= qt; k++) s += ps[k];
        sinv[tid] = 1.0f / s;
    }
    __syncthreads();

    float acc[4][2][4] = {};
    const int nkt = 4 * qt + 4;
    const float pinv = sinv[prow];

    const uint32_t bPh = smem_u32(sPh), bPl = smem_u32(sPl);
    const uint32_t bVh = smem_u32(sVh), bVl = smem_u32(sVl);

    for (int kt = 0; kt < nkt; kt++) {
        const int t0 = kt * 32;
        stage16_norm(attn + (size_t)bh * T * T + (size_t)(qt * 128 + prow) * T + t0 + pcb,
                     pinv, sPh + prow * 40 + pcb, sPl + prow * 40 + pcb);
        {
            const size_t voff = (size_t)(b * T + t0 + vrow) * C + h * 64 + vcb;
            *(uint4*)(sVh + vrow * 72 + vcb) = *(const uint4*)(vh + voff);
            *(uint4*)(sVl + vrow * 72 + vcb) = *(const uint4*)(vl + voff);
        }
        __syncthreads();

#pragma unroll
        for (int s = 0; s < 2; s++) {
            uint32_t afh[4][4], afl[4][4], fbh[2][2], fbl[2][2];
#pragma unroll
            for (int mf = 0; mf < 4; mf++) {
                uint32_t off = (uint32_t)(wm + mf * 16 + (lane & 15)) * 80 + s * 32 + ((lane >> 4) * 16);
                ldsm4(bPh + off, afh[mf]);
                ldsm4(bPl + off, afl[mf]);
            }
#pragma unroll
            for (int nf = 0; nf < 2; nf++) {
                uint32_t off = (uint32_t)(s * 16 + (lane & 15)) * 144 + (wn + nf * 8) * 2;
                ldsm2t(bVh + off, fbh[nf]);
                ldsm2t(bVl + off, fbl[nf]);
            }
#pragma unroll
            for (int mf = 0; mf < 4; mf++)
#pragma unroll
                for (int nf = 0; nf < 2; nf++) {
                    mma_bf16(acc[mf][nf], afh[mf], fbh[nf]);
                    mma_bf16(acc[mf][nf], afh[mf], fbl[nf]);
                    mma_bf16(acc[mf][nf], afl[mf], fbh[nf]);
                }
        }
        __syncthreads();
    }

#pragma unroll
    for (int mf = 0; mf < 4; mf++) {
        const int gr = b * T + qt * 128 + wm + mf * 16 + (lane >> 2);
#pragma unroll
        for (int nf = 0; nf < 2; nf++) {
            const int gc = h * 64 + wn + nf * 8 + (lane & 3) * 2;
            bf16 h0,h1,l0,l1;
            fsplit(acc[mf][nf][0], h0, l0); fsplit(acc[mf][nf][1], h1, l1);
            *(uint32_t*)(outh + (size_t)gr * C + gc) = pack2(h0, h1);
            *(uint32_t*)(outl + (size_t)gr * C + gc) = pack2(l0, l1);
            fsplit(acc[mf][nf][2], h0, l0); fsplit(acc[mf][nf][3], h1, l1);
            *(uint32_t*)(outh + (size_t)(gr + 8) * C + gc) = pack2(h0, h1);
            *(uint32_t*)(outl + (size_t)(gr + 8) * C + gc) = pack2(l0, l1);
        }
    }
}

// ---------------------------------------------------------------------------
extern "C" void kernel_launch(void* const* d_in, const int* in_sizes, int n_in,
                              void* d_out, int out_size) {
    const float* query = (const float*)d_in[0];
    const float* key   = (const float*)d_in[1];
    const float* value = (const float*)d_in[2];
    const unsigned char* kp = (const unsigned char*)d_in[4];
    const float* Wq = (const float*)d_in[5];  const float* bq = (const float*)d_in[6];
    const float* Wk = (const float*)d_in[7];  const float* bk = (const float*)d_in[8];
    const float* Wv = (const float*)d_in[9];  const float* bv = (const float*)d_in[10];
    const float* Wo = (const float*)d_in[11]; const float* bo = (const float*)d_in[12];

    float* y    = (float*)d_out;
    float* attn = y + (size_t)BT * C;   // tuple order: (y, attn_weights)

    bf16 *qh,*ql,*kh,*kl,*vh,*vl,*ah,*al;
    float* psum;
    cudaGetSymbolAddress((void**)&qh, g_qh); cudaGetSymbolAddress((void**)&ql, g_ql);
    cudaGetSymbolAddress((void**)&kh, g_kh); cudaGetSymbolAddress((void**)&kl, g_kl);
    cudaGetSymbolAddress((void**)&vh, g_vh); cudaGetSymbolAddress((void**)&vl, g_vl);
    cudaGetSymbolAddress((void**)&ah, g_ah); cudaGetSymbolAddress((void**)&al, g_al);
    cudaGetSymbolAddress((void**)&psum, g_psum);

    cudaFuncSetAttribute(proj_tc<0>, cudaFuncAttributeMaxDynamicSharedMemorySize, PROJ_SMEM);
    cudaFuncSetAttribute(proj_tc<1>, cudaFuncAttributeMaxDynamicSharedMemorySize, PROJ_SMEM);
    cudaFuncSetAttribute(scores_tc,  cudaFuncAttributeMaxDynamicSharedMemorySize, SCORES_SMEM);

    dim3 pg(C / 128, BT / 128);   // (8, 64)

    // projections (SCALE folded into Q)
    proj_tc<0><<<pg, 256, PROJ_SMEM>>>(query, nullptr, nullptr, Wq, bq, SCALE, nullptr, qh, ql);
    proj_tc<0><<<pg, 256, PROJ_SMEM>>>(key,   nullptr, nullptr, Wk, bk, 1.0f,  nullptr, kh, kl);
    proj_tc<0><<<pg, 256, PROJ_SMEM>>>(value, nullptr, nullptr, Wv, bv, 1.0f,  nullptr, vh, vl);

    // zero strictly-upper tiles (independent of scores)
    dim3 zg(256, B * H);
    zfill<<<zg, 256>>>(attn);

    // scores + exp + row partial sums (lower-triangle tiles)
    dim3 sg(T / 128, T / 128, B * H);
    scores_tc<<<sg, 256, SCORES_SMEM>>>(qh, ql, kh, kl, kp, attn, psum);

    // AV + in-place normalization of attn
    dim3 ag(T / 128, B * H);
    av_tc<<<ag, 256, AV_SMEM>>>(attn, psum, vh, vl, ah, al);

    // output projection
    proj_tc<1><<<pg, 256, PROJ_SMEM>>>(nullptr, ah, al, Wo, bo, 1.0f, y, nullptr, nullptr);
}